// round 2
// baseline (speedup 1.0000x reference)
#include <cuda_runtime.h>
#include <stdint.h>

#define NN 50000
#define NE 1600000
#define D  64

// ---------------- scratch (static device globals; no allocation) ----------------
__device__ __align__(16) float g_x0[NN * D];
__device__ __align__(16) float g_x1[NN * D];
__device__ __align__(16) float g_acc[NN * D];
__device__ float g_invdeg[NN];
__device__ int   g_deg[NN];
__device__ int   g_fill[NN];
__device__ int   g_rowstart[NN + 1];
__device__ int   g_src[NE];
__device__ int   g_dst[NE];
__device__ int   g_csr[NE];
__device__ int   g_is64;

// ---------------- dtype probe: int64 vs int32 edge_index ----------------
__global__ void detect_kernel(const long long* __restrict__ p) {
    if (threadIdx.x == 0 && blockIdx.x == 0) {
        int ok = 1;
        for (int i = 0; i < 256; i++) {
            long long v = p[i];
            if (v < 0 || v >= NN) { ok = 0; break; }
        }
        g_is64 = ok;
    }
}

// ---------------- zero counters ----------------
__global__ void zero_cnt_kernel() {
    int i = blockIdx.x * blockDim.x + threadIdx.x;
    if (i < NN) { g_deg[i] = 0; g_fill[i] = 0; }
}

// ---------------- edge prep: int64/int32 -> int32, degree count ----------------
__global__ void prep_edges_kernel(const void* __restrict__ ei) {
    int e = blockIdx.x * blockDim.x + threadIdx.x;
    if (e >= NE) return;
    int s, d;
    if (g_is64) {
        const long long* p = (const long long*)ei;
        s = (int)p[e];
        d = (int)p[NE + e];
    } else {
        const int* p = (const int*)ei;
        s = p[e];
        d = p[NE + e];
    }
    g_src[e] = s;
    g_dst[e] = d;
    atomicAdd(&g_deg[d], 1);
}

// ---------------- exclusive prefix sum over degrees (single block) ----------------
__global__ void scan_kernel() {
    __shared__ int ssum[1024];
    const int t  = threadIdx.x;
    const int CH = (NN + 1023) / 1024;  // 49
    int beg = t * CH;
    int end = beg + CH; if (end > NN) end = NN;
    int s = 0;
    for (int i = beg; i < end; i++) s += g_deg[i];
    ssum[t] = s;
    __syncthreads();
    // Hillis-Steele inclusive scan
    for (int off = 1; off < 1024; off <<= 1) {
        int v = (t >= off) ? ssum[t - off] : 0;
        __syncthreads();
        ssum[t] += v;
        __syncthreads();
    }
    int base = ssum[t] - s;  // exclusive
    for (int i = beg; i < end; i++) {
        g_rowstart[i] = base;
        base += g_deg[i];
    }
    if (t == 1023) g_rowstart[NN] = base;
}

__global__ void invdeg_kernel() {
    int i = blockIdx.x * blockDim.x + threadIdx.x;
    if (i < NN) g_invdeg[i] = 1.0f / fmaxf((float)g_deg[i], 1.0f);
}

// ---------------- CSR fill: csr[rowstart[dst] + k] = src ----------------
__global__ void csr_fill_kernel() {
    int e = blockIdx.x * blockDim.x + threadIdx.x;
    if (e >= NE) return;
    int d = g_dst[e];
    int slot = g_rowstart[d] + atomicAdd(&g_fill[d], 1);
    g_csr[slot] = g_src[e];
}

// ---------------- input projection: out[:, colOff:colOff+32] = X @ W + b ----------------
template <int DIN>
__global__ void proj_kernel(const float* __restrict__ X, const float* __restrict__ W,
                            const float* __restrict__ b, float* __restrict__ out, int colOff) {
    __shared__ float sA[64][33];
    __shared__ float sW[32][32];
    const int t  = threadIdx.x;
    const int i0 = blockIdx.x * 64;
    const int tx = t & 31;
    const int ty = t >> 5;

    float racc[8];
#pragma unroll
    for (int r = 0; r < 8; r++) racc[r] = 0.f;

    const int c4 = t & 7;   // float4 column within 32-wide tile
    const int rl = t >> 3;  // 0..31

    for (int k0 = 0; k0 < DIN; k0 += 32) {
#pragma unroll
        for (int p = 0; p < 2; p++) {
            int row = rl + p * 32;
            int gi  = i0 + row;
            float4 v = make_float4(0.f, 0.f, 0.f, 0.f);
            if (gi < NN)
                v = *reinterpret_cast<const float4*>(&X[(size_t)gi * DIN + k0 + c4 * 4]);
            sA[row][c4 * 4 + 0] = v.x;
            sA[row][c4 * 4 + 1] = v.y;
            sA[row][c4 * 4 + 2] = v.z;
            sA[row][c4 * 4 + 3] = v.w;
        }
        {
            float4 w = *reinterpret_cast<const float4*>(&W[(size_t)(k0 + rl) * 32 + c4 * 4]);
            sW[rl][c4 * 4 + 0] = w.x;
            sW[rl][c4 * 4 + 1] = w.y;
            sW[rl][c4 * 4 + 2] = w.z;
            sW[rl][c4 * 4 + 3] = w.w;
        }
        __syncthreads();
#pragma unroll
        for (int kk = 0; kk < 32; kk++) {
            float w = sW[kk][tx];
#pragma unroll
            for (int r = 0; r < 8; r++) racc[r] += sA[ty * 8 + r][kk] * w;
        }
        __syncthreads();
    }

    float bias = b[tx];
#pragma unroll
    for (int r = 0; r < 8; r++) {
        int gi = i0 + ty * 8 + r;
        if (gi < NN) out[(size_t)gi * D + colOff + tx] = racc[r] + bias;
    }
}

// ---------------- gather aggregation: acc[n] = invdeg[n] * sum_{s in nbrs(n)} xin[s] ----------------
// warp per node, float2 per lane (32 lanes x 2 = 64 floats), 2-neighbor unroll for MLP.
__global__ void aggregate_kernel(const float* __restrict__ xin) {
    int warp = (blockIdx.x * blockDim.x + threadIdx.x) >> 5;
    int lane = threadIdx.x & 31;
    if (warp >= NN) return;
    int beg = g_rowstart[warp];
    int end = g_rowstart[warp + 1];
    const float2* x2 = reinterpret_cast<const float2*>(xin);
    float ax = 0.f, ay = 0.f;
    int j = beg;
    for (; j + 3 < end; j += 4) {
        int s0 = g_csr[j], s1 = g_csr[j + 1], s2 = g_csr[j + 2], s3 = g_csr[j + 3];
        float2 v0 = __ldg(&x2[(size_t)s0 * 32 + lane]);
        float2 v1 = __ldg(&x2[(size_t)s1 * 32 + lane]);
        float2 v2 = __ldg(&x2[(size_t)s2 * 32 + lane]);
        float2 v3 = __ldg(&x2[(size_t)s3 * 32 + lane]);
        ax += (v0.x + v1.x) + (v2.x + v3.x);
        ay += (v0.y + v1.y) + (v2.y + v3.y);
    }
    for (; j < end; j++) {
        int s0 = g_csr[j];
        float2 v0 = __ldg(&x2[(size_t)s0 * 32 + lane]);
        ax += v0.x; ay += v0.y;
    }
    float id = g_invdeg[warp];
    reinterpret_cast<float2*>(g_acc)[(size_t)warp * 32 + lane] = make_float2(ax * id, ay * id);
}

// ---------------- SAGE layer GEMM: xout = relu(acc @ Wl + xin @ Wr + bl) ----------------
__global__ void layer_kernel(const float* __restrict__ xin, const float* __restrict__ Wl,
                             const float* __restrict__ bl, const float* __restrict__ Wr,
                             float* __restrict__ xout) {
    __shared__ float sA[64][65];
    __shared__ float sW[64][64];
    const int t  = threadIdx.x;
    const int i0 = blockIdx.x * 64;
    const int tx = t & 15;
    const int ty = t >> 4;

    float racc[4][4];
#pragma unroll
    for (int r = 0; r < 4; r++)
#pragma unroll
        for (int c = 0; c < 4; c++) racc[r][c] = 0.f;

    const int c4 = t & 15;
    const int r0 = t >> 4;

    for (int half = 0; half < 2; half++) {
        const float* srcmat = (half == 0) ? g_acc : xin;
        const float* Wm     = (half == 0) ? Wl : Wr;
#pragma unroll
        for (int p = 0; p < 4; p++) {
            int row = r0 + p * 16;
            int gi  = i0 + row;
            float4 v = make_float4(0.f, 0.f, 0.f, 0.f);
            if (gi < NN)
                v = *reinterpret_cast<const float4*>(&srcmat[(size_t)gi * D + c4 * 4]);
            sA[row][c4 * 4 + 0] = v.x;
            sA[row][c4 * 4 + 1] = v.y;
            sA[row][c4 * 4 + 2] = v.z;
            sA[row][c4 * 4 + 3] = v.w;
        }
#pragma unroll
        for (int p = 0; p < 4; p++) {
            int row = r0 + p * 16;
            float4 w = *reinterpret_cast<const float4*>(&Wm[(size_t)row * 64 + c4 * 4]);
            sW[row][c4 * 4 + 0] = w.x;
            sW[row][c4 * 4 + 1] = w.y;
            sW[row][c4 * 4 + 2] = w.z;
            sW[row][c4 * 4 + 3] = w.w;
        }
        __syncthreads();
#pragma unroll
        for (int kk = 0; kk < 64; kk++) {
            float4 bv = *reinterpret_cast<const float4*>(&sW[kk][tx * 4]);
            float a0 = sA[ty * 4 + 0][kk];
            float a1 = sA[ty * 4 + 1][kk];
            float a2 = sA[ty * 4 + 2][kk];
            float a3 = sA[ty * 4 + 3][kk];
            racc[0][0] += a0 * bv.x; racc[0][1] += a0 * bv.y; racc[0][2] += a0 * bv.z; racc[0][3] += a0 * bv.w;
            racc[1][0] += a1 * bv.x; racc[1][1] += a1 * bv.y; racc[1][2] += a1 * bv.z; racc[1][3] += a1 * bv.w;
            racc[2][0] += a2 * bv.x; racc[2][1] += a2 * bv.y; racc[2][2] += a2 * bv.z; racc[2][3] += a2 * bv.w;
            racc[3][0] += a3 * bv.x; racc[3][1] += a3 * bv.y; racc[3][2] += a3 * bv.z; racc[3][3] += a3 * bv.w;
        }
        __syncthreads();
    }

    float b0 = bl[tx * 4 + 0], b1 = bl[tx * 4 + 1], b2 = bl[tx * 4 + 2], b3 = bl[tx * 4 + 3];
#pragma unroll
    for (int r = 0; r < 4; r++) {
        int gi = i0 + ty * 4 + r;
        if (gi < NN) {
            float4 v;
            v.x = fmaxf(racc[r][0] + b0, 0.f);
            v.y = fmaxf(racc[r][1] + b1, 0.f);
            v.z = fmaxf(racc[r][2] + b2, 0.f);
            v.w = fmaxf(racc[r][3] + b3, 0.f);
            *reinterpret_cast<float4*>(&xout[(size_t)gi * D + tx * 4]) = v;
        }
    }
}

// ---------------- output head: out = x @ Wo + bo   ([N,64]@[64,2]) ----------------
__global__ void head_kernel(const float* __restrict__ x, const float* __restrict__ Wo,
                            const float* __restrict__ bo, float* __restrict__ out) {
    int gw   = (blockIdx.x * blockDim.x + threadIdx.x) >> 5;
    int lane = threadIdx.x & 31;
    if (gw >= NN) return;
    float xa = x[(size_t)gw * D + lane];
    float xb = x[(size_t)gw * D + 32 + lane];
    float p0 = xa * Wo[lane * 2 + 0] + xb * Wo[(lane + 32) * 2 + 0];
    float p1 = xa * Wo[lane * 2 + 1] + xb * Wo[(lane + 32) * 2 + 1];
#pragma unroll
    for (int o = 16; o > 0; o >>= 1) {
        p0 += __shfl_xor_sync(0xFFFFFFFFu, p0, o);
        p1 += __shfl_xor_sync(0xFFFFFFFFu, p1, o);
    }
    if (lane == 0) {
        out[gw * 2 + 0] = p0 + bo[0];
        out[gw * 2 + 1] = p1 + bo[1];
    }
}

// ---------------- launch ----------------
extern "C" void kernel_launch(void* const* d_in, const int* in_sizes, int n_in,
                              void* d_out, int out_size) {
    const float* x_content = (const float*)d_in[0];
    const float* x_style   = (const float*)d_in[1];
    const void*  edge_idx  = d_in[2];
    // d_in[3] = edge_type (unused by the model)
    const float* Wp  = (const float*)d_in[4];
    const float* bp  = (const float*)d_in[5];
    const float* Ws  = (const float*)d_in[6];
    const float* bs  = (const float*)d_in[7];
    const float* Wl1 = (const float*)d_in[8];
    const float* bl1 = (const float*)d_in[9];
    const float* Wr1 = (const float*)d_in[10];
    const float* Wl2 = (const float*)d_in[11];
    const float* bl2 = (const float*)d_in[12];
    const float* Wr2 = (const float*)d_in[13];
    const float* Wl3 = (const float*)d_in[14];
    const float* bl3 = (const float*)d_in[15];
    const float* Wr3 = (const float*)d_in[16];
    const float* Wo  = (const float*)d_in[17];
    const float* bo  = (const float*)d_in[18];
    float* out = (float*)d_out;

    float *x0, *x1;
    cudaGetSymbolAddress((void**)&x0, g_x0);
    cudaGetSymbolAddress((void**)&x1, g_x1);

    const int TPB = 256;

    // graph prep (CSR built once per replay)
    detect_kernel<<<1, 32>>>((const long long*)edge_idx);
    zero_cnt_kernel<<<(NN + TPB - 1) / TPB, TPB>>>();
    prep_edges_kernel<<<(NE + TPB - 1) / TPB, TPB>>>(edge_idx);
    scan_kernel<<<1, 1024>>>();
    invdeg_kernel<<<(NN + TPB - 1) / TPB, TPB>>>();
    csr_fill_kernel<<<(NE + TPB - 1) / TPB, TPB>>>();

    // input projection -> x0 [N,64]
    int projBlocks = (NN + 63) / 64;
    proj_kernel<768><<<projBlocks, TPB>>>(x_content, Wp, bp, x0, 0);
    proj_kernel<128><<<projBlocks, TPB>>>(x_style, Ws, bs, x0, 32);

    const int aggBlocks  = (NN * 32 + TPB - 1) / TPB;
    const int gemmBlocks = (NN + 63) / 64;

    // layer 1: x0 -> x1
    aggregate_kernel<<<aggBlocks, TPB>>>(x0);
    layer_kernel<<<gemmBlocks, TPB>>>(x0, Wl1, bl1, Wr1, x1);

    // layer 2: x1 -> x0
    aggregate_kernel<<<aggBlocks, TPB>>>(x1);
    layer_kernel<<<gemmBlocks, TPB>>>(x1, Wl2, bl2, Wr2, x0);

    // layer 3: x0 -> x1
    aggregate_kernel<<<aggBlocks, TPB>>>(x0);
    layer_kernel<<<gemmBlocks, TPB>>>(x0, Wl3, bl3, Wr3, x1);

    // head
    head_kernel<<<(NN * 32 + TPB - 1) / TPB, TPB>>>(x1, Wo, bo, out);
}

// round 3
// speedup vs baseline: 1.3649x; 1.3649x over previous
#include <cuda_runtime.h>
#include <stdint.h>

#define NN 50000
#define NE 1600000
#define D  64
#define NBLK 49   // ceil(NN/1024)

// ---------------- scratch (static device globals; no allocation) ----------------
__device__ __align__(16) float g_x0[NN * D];
__device__ __align__(16) float g_x1[NN * D];
__device__ __align__(16) float g_acc[NN * D];
__device__ float g_invdeg[NN];
__device__ int   g_deg[NN];
__device__ int   g_fill[NN];
__device__ int   g_rowstart[NN + 1];
__device__ int   g_src[NE];
__device__ int   g_dst[NE];
__device__ int   g_csr[NE];
__device__ int   g_is64;
__device__ int   g_blocksum[NBLK];
__device__ int   g_blockbase[NBLK];

// ---------------- dtype probe: int64 vs int32 edge_index ----------------
__global__ void detect_kernel(const long long* __restrict__ p) {
    int t = threadIdx.x;              // 256 threads
    long long v = p[t];
    int ok = (v >= 0 && v < NN) ? 1 : 0;
    int all = __syncthreads_and(ok);
    if (t == 0) g_is64 = all;
}

// ---------------- zero counters ----------------
__global__ void zero_cnt_kernel() {
    int i = blockIdx.x * blockDim.x + threadIdx.x;
    if (i < NN) { g_deg[i] = 0; g_fill[i] = 0; }
}

// ---------------- edge prep: int64/int32 -> int32, degree count ----------------
__global__ void prep_edges_kernel(const void* __restrict__ ei) {
    int e = blockIdx.x * blockDim.x + threadIdx.x;
    if (e >= NE) return;
    int s, d;
    if (g_is64) {
        const long long* p = (const long long*)ei;
        s = (int)p[e];
        d = (int)p[NE + e];
    } else {
        const int* p = (const int*)ei;
        s = p[e];
        d = p[NE + e];
    }
    g_src[e] = s;
    g_dst[e] = d;
    atomicAdd(&g_deg[d], 1);
}

// ---------------- parallel exclusive scan over degrees (3 phases) ----------------
__global__ void scan1_kernel() {      // grid NBLK x 1024: block sums
    __shared__ int sh[1024];
    int t = threadIdx.x;
    int i = blockIdx.x * 1024 + t;
    int v = (i < NN) ? g_deg[i] : 0;
    sh[t] = v;
    __syncthreads();
#pragma unroll
    for (int off = 512; off > 0; off >>= 1) {
        if (t < off) sh[t] += sh[t + off];
        __syncthreads();
    }
    if (t == 0) g_blocksum[blockIdx.x] = sh[0];
}

__global__ void scan2_kernel() {      // 1 block x 64: scan of block sums
    __shared__ int sh[64];
    int t = threadIdx.x;
    int v = (t < NBLK) ? g_blocksum[t] : 0;
    sh[t] = v;
    __syncthreads();
#pragma unroll
    for (int off = 1; off < 64; off <<= 1) {
        int u = (t >= off) ? sh[t - off] : 0;
        __syncthreads();
        sh[t] += u;
        __syncthreads();
    }
    if (t < NBLK) g_blockbase[t] = sh[t] - v;   // exclusive base per block
    if (t == NBLK - 1) g_rowstart[NN] = sh[t];  // total = NE
}

__global__ void scan3_kernel() {      // grid NBLK x 1024: in-block scan + invdeg
    __shared__ int sh[1024];
    int t = threadIdx.x;
    int i = blockIdx.x * 1024 + t;
    int v = (i < NN) ? g_deg[i] : 0;
    sh[t] = v;
    __syncthreads();
#pragma unroll
    for (int off = 1; off < 1024; off <<= 1) {
        int u = (t >= off) ? sh[t - off] : 0;
        __syncthreads();
        sh[t] += u;
        __syncthreads();
    }
    if (i < NN) {
        g_rowstart[i] = g_blockbase[blockIdx.x] + sh[t] - v;
        g_invdeg[i] = 1.0f / fmaxf((float)v, 1.0f);
    }
}

// ---------------- CSR fill: csr[rowstart[dst] + k] = src ----------------
__global__ void csr_fill_kernel() {
    int e = blockIdx.x * blockDim.x + threadIdx.x;
    if (e >= NE) return;
    int d = g_dst[e];
    int slot = g_rowstart[d] + atomicAdd(&g_fill[d], 1);
    g_csr[slot] = g_src[e];
}

// ---------------- input projection: out[:, colOff:colOff+32] = X @ W + b ----------------
// BM=128 rows, BN=32 cols, BK=32. 256 threads; 4x4 micro-tile per thread.
template <int DIN>
__global__ void proj_kernel(const float* __restrict__ X, const float* __restrict__ W,
                            const float* __restrict__ b, float* __restrict__ out, int colOff) {
    __shared__ float sA[128][33];
    __shared__ float sW[32][32];
    const int t  = threadIdx.x;
    const int i0 = blockIdx.x * 128;
    const int tx = t & 7;    // col quad: cols tx*4 .. tx*4+3
    const int ty = t >> 3;   // 0..31: rows ty*4 .. ty*4+3

    float racc[4][4];
#pragma unroll
    for (int r = 0; r < 4; r++)
#pragma unroll
        for (int c = 0; c < 4; c++) racc[r][c] = 0.f;

    const int c4 = t & 7;    // float4 column within 32-wide K tile
    const int rl = t >> 3;   // 0..31

    for (int k0 = 0; k0 < DIN; k0 += 32) {
        // load A tile 128x32 (4 passes of 32 rows)
#pragma unroll
        for (int p = 0; p < 4; p++) {
            int row = rl + p * 32;
            int gi  = i0 + row;
            float4 v = make_float4(0.f, 0.f, 0.f, 0.f);
            if (gi < NN)
                v = *reinterpret_cast<const float4*>(&X[(size_t)gi * DIN + k0 + c4 * 4]);
            sA[row][c4 * 4 + 0] = v.x;
            sA[row][c4 * 4 + 1] = v.y;
            sA[row][c4 * 4 + 2] = v.z;
            sA[row][c4 * 4 + 3] = v.w;
        }
        // load W tile 32x32
        {
            float4 w = *reinterpret_cast<const float4*>(&W[(size_t)(k0 + rl) * 32 + c4 * 4]);
            sW[rl][c4 * 4 + 0] = w.x;
            sW[rl][c4 * 4 + 1] = w.y;
            sW[rl][c4 * 4 + 2] = w.z;
            sW[rl][c4 * 4 + 3] = w.w;
        }
        __syncthreads();
#pragma unroll
        for (int kk = 0; kk < 32; kk++) {
            float4 wv = *reinterpret_cast<const float4*>(&sW[kk][tx * 4]);
            float a0 = sA[ty * 4 + 0][kk];
            float a1 = sA[ty * 4 + 1][kk];
            float a2 = sA[ty * 4 + 2][kk];
            float a3 = sA[ty * 4 + 3][kk];
            racc[0][0] += a0 * wv.x; racc[0][1] += a0 * wv.y; racc[0][2] += a0 * wv.z; racc[0][3] += a0 * wv.w;
            racc[1][0] += a1 * wv.x; racc[1][1] += a1 * wv.y; racc[1][2] += a1 * wv.z; racc[1][3] += a1 * wv.w;
            racc[2][0] += a2 * wv.x; racc[2][1] += a2 * wv.y; racc[2][2] += a2 * wv.z; racc[2][3] += a2 * wv.w;
            racc[3][0] += a3 * wv.x; racc[3][1] += a3 * wv.y; racc[3][2] += a3 * wv.z; racc[3][3] += a3 * wv.w;
        }
        __syncthreads();
    }

    float b0 = b[tx * 4 + 0], b1 = b[tx * 4 + 1], b2 = b[tx * 4 + 2], b3 = b[tx * 4 + 3];
#pragma unroll
    for (int r = 0; r < 4; r++) {
        int gi = i0 + ty * 4 + r;
        if (gi < NN) {
            float4 v;
            v.x = racc[r][0] + b0;
            v.y = racc[r][1] + b1;
            v.z = racc[r][2] + b2;
            v.w = racc[r][3] + b3;
            *reinterpret_cast<float4*>(&out[(size_t)gi * D + colOff + tx * 4]) = v;
        }
    }
}

// ---------------- gather aggregation: acc[n] = invdeg[n] * sum_{s in nbrs(n)} xin[s] ----------------
// warp per node; lanes 0-15 handle even neighbors, lanes 16-31 odd neighbors; float4 per lane.
__global__ void aggregate_kernel(const float* __restrict__ xin) {
    int warp = (blockIdx.x * blockDim.x + threadIdx.x) >> 5;
    int lane = threadIdx.x & 31;
    if (warp >= NN) return;
    const int half = lane >> 4;   // 0 or 1
    const int l16  = lane & 15;
    int beg = g_rowstart[warp];
    int end = g_rowstart[warp + 1];
    const float4* x4 = reinterpret_cast<const float4*>(xin);
    float4 acc = make_float4(0.f, 0.f, 0.f, 0.f);
    int j = beg + half;
    // 2 pair-steps in flight (4 neighbors warp-wide)
    for (; j + 2 < end; j += 4) {
        int s0 = g_csr[j];
        int s1 = g_csr[j + 2];
        float4 v0 = __ldg(&x4[(size_t)s0 * 16 + l16]);
        float4 v1 = __ldg(&x4[(size_t)s1 * 16 + l16]);
        acc.x += v0.x + v1.x;
        acc.y += v0.y + v1.y;
        acc.z += v0.z + v1.z;
        acc.w += v0.w + v1.w;
    }
    if (j < end) {
        int s0 = g_csr[j];
        float4 v0 = __ldg(&x4[(size_t)s0 * 16 + l16]);
        acc.x += v0.x; acc.y += v0.y; acc.z += v0.z; acc.w += v0.w;
    }
    // combine the two neighbor streams across half-warps
    acc.x += __shfl_xor_sync(0xFFFFFFFFu, acc.x, 16);
    acc.y += __shfl_xor_sync(0xFFFFFFFFu, acc.y, 16);
    acc.z += __shfl_xor_sync(0xFFFFFFFFu, acc.z, 16);
    acc.w += __shfl_xor_sync(0xFFFFFFFFu, acc.w, 16);
    if (half == 0) {
        float id = g_invdeg[warp];
        acc.x *= id; acc.y *= id; acc.z *= id; acc.w *= id;
        reinterpret_cast<float4*>(g_acc)[(size_t)warp * 16 + l16] = acc;
    }
}

// ---------------- SAGE layer GEMM: xout = relu(acc @ Wl + xin @ Wr + bl) ----------------
__global__ void layer_kernel(const float* __restrict__ xin, const float* __restrict__ Wl,
                             const float* __restrict__ bl, const float* __restrict__ Wr,
                             float* __restrict__ xout) {
    __shared__ float sA[64][65];
    __shared__ float sW[64][64];
    const int t  = threadIdx.x;
    const int i0 = blockIdx.x * 64;
    const int tx = t & 15;
    const int ty = t >> 4;

    float racc[4][4];
#pragma unroll
    for (int r = 0; r < 4; r++)
#pragma unroll
        for (int c = 0; c < 4; c++) racc[r][c] = 0.f;

    const int c4 = t & 15;
    const int r0 = t >> 4;

    for (int half = 0; half < 2; half++) {
        const float* srcmat = (half == 0) ? g_acc : xin;
        const float* Wm     = (half == 0) ? Wl : Wr;
#pragma unroll
        for (int p = 0; p < 4; p++) {
            int row = r0 + p * 16;
            int gi  = i0 + row;
            float4 v = make_float4(0.f, 0.f, 0.f, 0.f);
            if (gi < NN)
                v = *reinterpret_cast<const float4*>(&srcmat[(size_t)gi * D + c4 * 4]);
            sA[row][c4 * 4 + 0] = v.x;
            sA[row][c4 * 4 + 1] = v.y;
            sA[row][c4 * 4 + 2] = v.z;
            sA[row][c4 * 4 + 3] = v.w;
        }
#pragma unroll
        for (int p = 0; p < 4; p++) {
            int row = r0 + p * 16;
            float4 w = *reinterpret_cast<const float4*>(&Wm[(size_t)row * 64 + c4 * 4]);
            sW[row][c4 * 4 + 0] = w.x;
            sW[row][c4 * 4 + 1] = w.y;
            sW[row][c4 * 4 + 2] = w.z;
            sW[row][c4 * 4 + 3] = w.w;
        }
        __syncthreads();
#pragma unroll
        for (int kk = 0; kk < 64; kk++) {
            float4 bv = *reinterpret_cast<const float4*>(&sW[kk][tx * 4]);
            float a0 = sA[ty * 4 + 0][kk];
            float a1 = sA[ty * 4 + 1][kk];
            float a2 = sA[ty * 4 + 2][kk];
            float a3 = sA[ty * 4 + 3][kk];
            racc[0][0] += a0 * bv.x; racc[0][1] += a0 * bv.y; racc[0][2] += a0 * bv.z; racc[0][3] += a0 * bv.w;
            racc[1][0] += a1 * bv.x; racc[1][1] += a1 * bv.y; racc[1][2] += a1 * bv.z; racc[1][3] += a1 * bv.w;
            racc[2][0] += a2 * bv.x; racc[2][1] += a2 * bv.y; racc[2][2] += a2 * bv.z; racc[2][3] += a2 * bv.w;
            racc[3][0] += a3 * bv.x; racc[3][1] += a3 * bv.y; racc[3][2] += a3 * bv.z; racc[3][3] += a3 * bv.w;
        }
        __syncthreads();
    }

    float b0 = bl[tx * 4 + 0], b1 = bl[tx * 4 + 1], b2 = bl[tx * 4 + 2], b3 = bl[tx * 4 + 3];
#pragma unroll
    for (int r = 0; r < 4; r++) {
        int gi = i0 + ty * 4 + r;
        if (gi < NN) {
            float4 v;
            v.x = fmaxf(racc[r][0] + b0, 0.f);
            v.y = fmaxf(racc[r][1] + b1, 0.f);
            v.z = fmaxf(racc[r][2] + b2, 0.f);
            v.w = fmaxf(racc[r][3] + b3, 0.f);
            *reinterpret_cast<float4*>(&xout[(size_t)gi * D + tx * 4]) = v;
        }
    }
}

// ---------------- output head: out = x @ Wo + bo   ([N,64]@[64,2]) ----------------
__global__ void head_kernel(const float* __restrict__ x, const float* __restrict__ Wo,
                            const float* __restrict__ bo, float* __restrict__ out) {
    int gw   = (blockIdx.x * blockDim.x + threadIdx.x) >> 5;
    int lane = threadIdx.x & 31;
    if (gw >= NN) return;
    float xa = x[(size_t)gw * D + lane];
    float xb = x[(size_t)gw * D + 32 + lane];
    float p0 = xa * Wo[lane * 2 + 0] + xb * Wo[(lane + 32) * 2 + 0];
    float p1 = xa * Wo[lane * 2 + 1] + xb * Wo[(lane + 32) * 2 + 1];
#pragma unroll
    for (int o = 16; o > 0; o >>= 1) {
        p0 += __shfl_xor_sync(0xFFFFFFFFu, p0, o);
        p1 += __shfl_xor_sync(0xFFFFFFFFu, p1, o);
    }
    if (lane == 0) {
        out[gw * 2 + 0] = p0 + bo[0];
        out[gw * 2 + 1] = p1 + bo[1];
    }
}

// ---------------- launch ----------------
extern "C" void kernel_launch(void* const* d_in, const int* in_sizes, int n_in,
                              void* d_out, int out_size) {
    const float* x_content = (const float*)d_in[0];
    const float* x_style   = (const float*)d_in[1];
    const void*  edge_idx  = d_in[2];
    // d_in[3] = edge_type (unused by the model)
    const float* Wp  = (const float*)d_in[4];
    const float* bp  = (const float*)d_in[5];
    const float* Ws  = (const float*)d_in[6];
    const float* bs  = (const float*)d_in[7];
    const float* Wl1 = (const float*)d_in[8];
    const float* bl1 = (const float*)d_in[9];
    const float* Wr1 = (const float*)d_in[10];
    const float* Wl2 = (const float*)d_in[11];
    const float* bl2 = (const float*)d_in[12];
    const float* Wr2 = (const float*)d_in[13];
    const float* Wl3 = (const float*)d_in[14];
    const float* bl3 = (const float*)d_in[15];
    const float* Wr3 = (const float*)d_in[16];
    const float* Wo  = (const float*)d_in[17];
    const float* bo  = (const float*)d_in[18];
    float* out = (float*)d_out;

    float *x0, *x1;
    cudaGetSymbolAddress((void**)&x0, g_x0);
    cudaGetSymbolAddress((void**)&x1, g_x1);

    const int TPB = 256;

    // graph prep (CSR rebuilt every replay: deterministic work)
    detect_kernel<<<1, 256>>>((const long long*)edge_idx);
    zero_cnt_kernel<<<(NN + TPB - 1) / TPB, TPB>>>();
    prep_edges_kernel<<<(NE + TPB - 1) / TPB, TPB>>>(edge_idx);
    scan1_kernel<<<NBLK, 1024>>>();
    scan2_kernel<<<1, 64>>>();
    scan3_kernel<<<NBLK, 1024>>>();
    csr_fill_kernel<<<(NE + TPB - 1) / TPB, TPB>>>();

    // input projection -> x0 [N,64]
    int projBlocks = (NN + 127) / 128;
    proj_kernel<768><<<projBlocks, TPB>>>(x_content, Wp, bp, x0, 0);
    proj_kernel<128><<<projBlocks, TPB>>>(x_style, Ws, bs, x0, 32);

    const int aggBlocks  = (NN * 32 + TPB - 1) / TPB;
    const int gemmBlocks = (NN + 63) / 64;

    // layer 1: x0 -> x1
    aggregate_kernel<<<aggBlocks, TPB>>>(x0);
    layer_kernel<<<gemmBlocks, TPB>>>(x0, Wl1, bl1, Wr1, x1);

    // layer 2: x1 -> x0
    aggregate_kernel<<<aggBlocks, TPB>>>(x1);
    layer_kernel<<<gemmBlocks, TPB>>>(x1, Wl2, bl2, Wr2, x0);

    // layer 3: x0 -> x1
    aggregate_kernel<<<aggBlocks, TPB>>>(x0);
    layer_kernel<<<gemmBlocks, TPB>>>(x0, Wl3, bl3, Wr3, x1);

    // head
    head_kernel<<<(NN * 32 + TPB - 1) / TPB, TPB>>>(x1, Wo, bo, out);
}

// round 4
// speedup vs baseline: 1.3651x; 1.0001x over previous
#include <cuda_runtime.h>
#include <cuda_fp16.h>
#include <stdint.h>

#define NN 50000
#define NE 1600000
#define D  64
#define NBLK 49   // ceil(NN/1024)

// ---------------- scratch (static device globals; no allocation) ----------------
__device__ __align__(16) float  g_x0[NN * D];
__device__ __align__(16) float  g_x1[NN * D];
__device__ __align__(16) __half g_h0[NN * D];   // fp16 shadow of x0
__device__ __align__(16) __half g_h1[NN * D];   // fp16 shadow of x1
__device__ __align__(16) float  g_acc[NN * D];
__device__ float g_invdeg[NN];
__device__ int   g_deg[NN];
__device__ int   g_fill[NN];
__device__ int   g_rowstart[NN + 1];
__device__ int   g_src[NE];
__device__ int   g_dst[NE];
__device__ int   g_csr[NE];
__device__ int   g_is64;
__device__ int   g_blocksum[NBLK];
__device__ int   g_blockbase[NBLK];

// ---------------- dtype probe: int64 vs int32 edge_index ----------------
__global__ void detect_kernel(const long long* __restrict__ p) {
    int t = threadIdx.x;              // 256 threads
    long long v = p[t];
    int ok = (v >= 0 && v < NN) ? 1 : 0;
    int all = __syncthreads_and(ok);
    if (t == 0) g_is64 = all;
}

// ---------------- zero counters ----------------
__global__ void zero_cnt_kernel() {
    int i = blockIdx.x * blockDim.x + threadIdx.x;
    if (i < NN) { g_deg[i] = 0; g_fill[i] = 0; }
}

// ---------------- edge prep: int64/int32 -> int32, degree count ----------------
__global__ void prep_edges_kernel(const void* __restrict__ ei) {
    int e = blockIdx.x * blockDim.x + threadIdx.x;
    if (e >= NE) return;
    int s, d;
    if (g_is64) {
        const long long* p = (const long long*)ei;
        s = (int)p[e];
        d = (int)p[NE + e];
    } else {
        const int* p = (const int*)ei;
        s = p[e];
        d = p[NE + e];
    }
    g_src[e] = s;
    g_dst[e] = d;
    atomicAdd(&g_deg[d], 1);
}

// ---------------- parallel exclusive scan over degrees (3 phases) ----------------
__global__ void scan1_kernel() {      // grid NBLK x 1024: block sums
    __shared__ int sh[1024];
    int t = threadIdx.x;
    int i = blockIdx.x * 1024 + t;
    int v = (i < NN) ? g_deg[i] : 0;
    sh[t] = v;
    __syncthreads();
#pragma unroll
    for (int off = 512; off > 0; off >>= 1) {
        if (t < off) sh[t] += sh[t + off];
        __syncthreads();
    }
    if (t == 0) g_blocksum[blockIdx.x] = sh[0];
}

__global__ void scan2_kernel() {      // 1 block x 64: scan of block sums
    __shared__ int sh[64];
    int t = threadIdx.x;
    int v = (t < NBLK) ? g_blocksum[t] : 0;
    sh[t] = v;
    __syncthreads();
#pragma unroll
    for (int off = 1; off < 64; off <<= 1) {
        int u = (t >= off) ? sh[t - off] : 0;
        __syncthreads();
        sh[t] += u;
        __syncthreads();
    }
    if (t < NBLK) g_blockbase[t] = sh[t] - v;   // exclusive base per block
    if (t == NBLK - 1) g_rowstart[NN] = sh[t];  // total = NE
}

__global__ void scan3_kernel() {      // grid NBLK x 1024: in-block scan + invdeg
    __shared__ int sh[1024];
    int t = threadIdx.x;
    int i = blockIdx.x * 1024 + t;
    int v = (i < NN) ? g_deg[i] : 0;
    sh[t] = v;
    __syncthreads();
#pragma unroll
    for (int off = 1; off < 1024; off <<= 1) {
        int u = (t >= off) ? sh[t - off] : 0;
        __syncthreads();
        sh[t] += u;
        __syncthreads();
    }
    if (i < NN) {
        g_rowstart[i] = g_blockbase[blockIdx.x] + sh[t] - v;
        g_invdeg[i] = 1.0f / fmaxf((float)v, 1.0f);
    }
}

// ---------------- CSR fill: csr[rowstart[dst] + k] = src ----------------
__global__ void csr_fill_kernel() {
    int e = blockIdx.x * blockDim.x + threadIdx.x;
    if (e >= NE) return;
    int d = g_dst[e];
    int slot = g_rowstart[d] + atomicAdd(&g_fill[d], 1);
    g_csr[slot] = g_src[e];
}

// ---------------- pack 4 floats into 4 halves (uint2) ----------------
__device__ __forceinline__ uint2 pack_half4(float a, float b, float c, float d) {
    __half2 lo = __floats2half2_rn(a, b);
    __half2 hi = __floats2half2_rn(c, d);
    uint2 r;
    r.x = *reinterpret_cast<uint32_t*>(&lo);
    r.y = *reinterpret_cast<uint32_t*>(&hi);
    return r;
}

// ---------------- input projection: out[:, colOff:colOff+32] = X @ W + b (+ fp16 shadow) ------
// BM=128 rows, BN=32 cols, BK=32. 256 threads; 4x4 micro-tile per thread.
template <int DIN>
__global__ void proj_kernel(const float* __restrict__ X, const float* __restrict__ W,
                            const float* __restrict__ b, float* __restrict__ out,
                            __half* __restrict__ hout, int colOff) {
    __shared__ float sA[128][33];
    __shared__ float sW[32][32];
    const int t  = threadIdx.x;
    const int i0 = blockIdx.x * 128;
    const int tx = t & 7;    // col quad: cols tx*4 .. tx*4+3
    const int ty = t >> 3;   // 0..31: rows ty*4 .. ty*4+3

    float racc[4][4];
#pragma unroll
    for (int r = 0; r < 4; r++)
#pragma unroll
        for (int c = 0; c < 4; c++) racc[r][c] = 0.f;

    const int c4 = t & 7;
    const int rl = t >> 3;

    for (int k0 = 0; k0 < DIN; k0 += 32) {
#pragma unroll
        for (int p = 0; p < 4; p++) {
            int row = rl + p * 32;
            int gi  = i0 + row;
            float4 v = make_float4(0.f, 0.f, 0.f, 0.f);
            if (gi < NN)
                v = *reinterpret_cast<const float4*>(&X[(size_t)gi * DIN + k0 + c4 * 4]);
            sA[row][c4 * 4 + 0] = v.x;
            sA[row][c4 * 4 + 1] = v.y;
            sA[row][c4 * 4 + 2] = v.z;
            sA[row][c4 * 4 + 3] = v.w;
        }
        {
            float4 w = *reinterpret_cast<const float4*>(&W[(size_t)(k0 + rl) * 32 + c4 * 4]);
            sW[rl][c4 * 4 + 0] = w.x;
            sW[rl][c4 * 4 + 1] = w.y;
            sW[rl][c4 * 4 + 2] = w.z;
            sW[rl][c4 * 4 + 3] = w.w;
        }
        __syncthreads();
#pragma unroll
        for (int kk = 0; kk < 32; kk++) {
            float4 wv = *reinterpret_cast<const float4*>(&sW[kk][tx * 4]);
            float a0 = sA[ty * 4 + 0][kk];
            float a1 = sA[ty * 4 + 1][kk];
            float a2 = sA[ty * 4 + 2][kk];
            float a3 = sA[ty * 4 + 3][kk];
            racc[0][0] += a0 * wv.x; racc[0][1] += a0 * wv.y; racc[0][2] += a0 * wv.z; racc[0][3] += a0 * wv.w;
            racc[1][0] += a1 * wv.x; racc[1][1] += a1 * wv.y; racc[1][2] += a1 * wv.z; racc[1][3] += a1 * wv.w;
            racc[2][0] += a2 * wv.x; racc[2][1] += a2 * wv.y; racc[2][2] += a2 * wv.z; racc[2][3] += a2 * wv.w;
            racc[3][0] += a3 * wv.x; racc[3][1] += a3 * wv.y; racc[3][2] += a3 * wv.z; racc[3][3] += a3 * wv.w;
        }
        __syncthreads();
    }

    float b0 = b[tx * 4 + 0], b1 = b[tx * 4 + 1], b2 = b[tx * 4 + 2], b3 = b[tx * 4 + 3];
#pragma unroll
    for (int r = 0; r < 4; r++) {
        int gi = i0 + ty * 4 + r;
        if (gi < NN) {
            float4 v;
            v.x = racc[r][0] + b0;
            v.y = racc[r][1] + b1;
            v.z = racc[r][2] + b2;
            v.w = racc[r][3] + b3;
            *reinterpret_cast<float4*>(&out[(size_t)gi * D + colOff + tx * 4]) = v;
            *reinterpret_cast<uint2*>(&hout[(size_t)gi * D + colOff + tx * 4]) =
                pack_half4(v.x, v.y, v.z, v.w);
        }
    }
}

// ---------------- gather aggregation (fp16 rows): acc[n] = invdeg[n]*sum xin_h[s] --------------
// warp per node; 4 neighbor streams x 8 lanes; lane loads uint4 = 8 halves (16B); row = 128B.
__global__ void aggregate_kernel(const __half* __restrict__ hin) {
    int warp = (blockIdx.x * blockDim.x + threadIdx.x) >> 5;
    int lane = threadIdx.x & 31;
    if (warp >= NN) return;
    const int q  = lane >> 3;   // stream 0..3
    const int l8 = lane & 7;    // 8-half chunk within row
    int beg = g_rowstart[warp];
    int end = g_rowstart[warp + 1];
    const uint4* h8 = reinterpret_cast<const uint4*>(hin);   // 8 rows-chunks of 8 halves

    float acc[8];
#pragma unroll
    for (int k = 0; k < 8; k++) acc[k] = 0.f;

    int j = beg + q;
    for (; j + 4 < end; j += 8) {
        int s0 = g_csr[j];
        int s1 = g_csr[j + 4];
        uint4 a = __ldg(&h8[(size_t)s0 * 8 + l8]);
        uint4 b = __ldg(&h8[(size_t)s1 * 8 + l8]);
#pragma unroll
        for (int w = 0; w < 4; w++) {
            uint32_t ua = (&a.x)[w];
            uint32_t ub = (&b.x)[w];
            float2 fa = __half22float2(*reinterpret_cast<__half2*>(&ua));
            float2 fb = __half22float2(*reinterpret_cast<__half2*>(&ub));
            acc[w * 2 + 0] += fa.x + fb.x;
            acc[w * 2 + 1] += fa.y + fb.y;
        }
    }
    if (j < end) {
        int s0 = g_csr[j];
        uint4 a = __ldg(&h8[(size_t)s0 * 8 + l8]);
#pragma unroll
        for (int w = 0; w < 4; w++) {
            uint32_t ua = (&a.x)[w];
            float2 fa = __half22float2(*reinterpret_cast<__half2*>(&ua));
            acc[w * 2 + 0] += fa.x;
            acc[w * 2 + 1] += fa.y;
        }
    }
    // combine 4 streams
#pragma unroll
    for (int k = 0; k < 8; k++) {
        acc[k] += __shfl_xor_sync(0xFFFFFFFFu, acc[k], 8);
        acc[k] += __shfl_xor_sync(0xFFFFFFFFu, acc[k], 16);
    }
    if (q == 0) {
        float id = g_invdeg[warp];
        float4 v0 = make_float4(acc[0] * id, acc[1] * id, acc[2] * id, acc[3] * id);
        float4 v1 = make_float4(acc[4] * id, acc[5] * id, acc[6] * id, acc[7] * id);
        float4* dst = reinterpret_cast<float4*>(&g_acc[(size_t)warp * D + l8 * 8]);
        dst[0] = v0;
        dst[1] = v1;
    }
}

// ---------------- SAGE layer GEMM: xout = relu(acc @ Wl + xin @ Wr + bl) (+ fp16 shadow) ------
__global__ void layer_kernel(const float* __restrict__ xin, const float* __restrict__ Wl,
                             const float* __restrict__ bl, const float* __restrict__ Wr,
                             float* __restrict__ xout, __half* __restrict__ hout) {
    __shared__ float sA[64][65];
    __shared__ float sW[64][64];
    const int t  = threadIdx.x;
    const int i0 = blockIdx.x * 64;
    const int tx = t & 15;
    const int ty = t >> 4;

    float racc[4][4];
#pragma unroll
    for (int r = 0; r < 4; r++)
#pragma unroll
        for (int c = 0; c < 4; c++) racc[r][c] = 0.f;

    const int c4 = t & 15;
    const int r0 = t >> 4;

    for (int half = 0; half < 2; half++) {
        const float* srcmat = (half == 0) ? g_acc : xin;
        const float* Wm     = (half == 0) ? Wl : Wr;
#pragma unroll
        for (int p = 0; p < 4; p++) {
            int row = r0 + p * 16;
            int gi  = i0 + row;
            float4 v = make_float4(0.f, 0.f, 0.f, 0.f);
            if (gi < NN)
                v = *reinterpret_cast<const float4*>(&srcmat[(size_t)gi * D + c4 * 4]);
            sA[row][c4 * 4 + 0] = v.x;
            sA[row][c4 * 4 + 1] = v.y;
            sA[row][c4 * 4 + 2] = v.z;
            sA[row][c4 * 4 + 3] = v.w;
        }
#pragma unroll
        for (int p = 0; p < 4; p++) {
            int row = r0 + p * 16;
            float4 w = *reinterpret_cast<const float4*>(&Wm[(size_t)row * 64 + c4 * 4]);
            sW[row][c4 * 4 + 0] = w.x;
            sW[row][c4 * 4 + 1] = w.y;
            sW[row][c4 * 4 + 2] = w.z;
            sW[row][c4 * 4 + 3] = w.w;
        }
        __syncthreads();
#pragma unroll
        for (int kk = 0; kk < 64; kk++) {
            float4 bv = *reinterpret_cast<const float4*>(&sW[kk][tx * 4]);
            float a0 = sA[ty * 4 + 0][kk];
            float a1 = sA[ty * 4 + 1][kk];
            float a2 = sA[ty * 4 + 2][kk];
            float a3 = sA[ty * 4 + 3][kk];
            racc[0][0] += a0 * bv.x; racc[0][1] += a0 * bv.y; racc[0][2] += a0 * bv.z; racc[0][3] += a0 * bv.w;
            racc[1][0] += a1 * bv.x; racc[1][1] += a1 * bv.y; racc[1][2] += a1 * bv.z; racc[1][3] += a1 * bv.w;
            racc[2][0] += a2 * bv.x; racc[2][1] += a2 * bv.y; racc[2][2] += a2 * bv.z; racc[2][3] += a2 * bv.w;
            racc[3][0] += a3 * bv.x; racc[3][1] += a3 * bv.y; racc[3][2] += a3 * bv.z; racc[3][3] += a3 * bv.w;
        }
        __syncthreads();
    }

    float b0 = bl[tx * 4 + 0], b1 = bl[tx * 4 + 1], b2 = bl[tx * 4 + 2], b3 = bl[tx * 4 + 3];
#pragma unroll
    for (int r = 0; r < 4; r++) {
        int gi = i0 + ty * 4 + r;
        if (gi < NN) {
            float4 v;
            v.x = fmaxf(racc[r][0] + b0, 0.f);
            v.y = fmaxf(racc[r][1] + b1, 0.f);
            v.z = fmaxf(racc[r][2] + b2, 0.f);
            v.w = fmaxf(racc[r][3] + b3, 0.f);
            *reinterpret_cast<float4*>(&xout[(size_t)gi * D + tx * 4]) = v;
            if (hout)
                *reinterpret_cast<uint2*>(&hout[(size_t)gi * D + tx * 4]) =
                    pack_half4(v.x, v.y, v.z, v.w);
        }
    }
}

// ---------------- output head: out = x @ Wo + bo   ([N,64]@[64,2]) ----------------
__global__ void head_kernel(const float* __restrict__ x, const float* __restrict__ Wo,
                            const float* __restrict__ bo, float* __restrict__ out) {
    int gw   = (blockIdx.x * blockDim.x + threadIdx.x) >> 5;
    int lane = threadIdx.x & 31;
    if (gw >= NN) return;
    float xa = x[(size_t)gw * D + lane];
    float xb = x[(size_t)gw * D + 32 + lane];
    float p0 = xa * Wo[lane * 2 + 0] + xb * Wo[(lane + 32) * 2 + 0];
    float p1 = xa * Wo[lane * 2 + 1] + xb * Wo[(lane + 32) * 2 + 1];
#pragma unroll
    for (int o = 16; o > 0; o >>= 1) {
        p0 += __shfl_xor_sync(0xFFFFFFFFu, p0, o);
        p1 += __shfl_xor_sync(0xFFFFFFFFu, p1, o);
    }
    if (lane == 0) {
        out[gw * 2 + 0] = p0 + bo[0];
        out[gw * 2 + 1] = p1 + bo[1];
    }
}

// ---------------- launch ----------------
extern "C" void kernel_launch(void* const* d_in, const int* in_sizes, int n_in,
                              void* d_out, int out_size) {
    const float* x_content = (const float*)d_in[0];
    const float* x_style   = (const float*)d_in[1];
    const void*  edge_idx  = d_in[2];
    // d_in[3] = edge_type (unused by the model)
    const float* Wp  = (const float*)d_in[4];
    const float* bp  = (const float*)d_in[5];
    const float* Ws  = (const float*)d_in[6];
    const float* bs  = (const float*)d_in[7];
    const float* Wl1 = (const float*)d_in[8];
    const float* bl1 = (const float*)d_in[9];
    const float* Wr1 = (const float*)d_in[10];
    const float* Wl2 = (const float*)d_in[11];
    const float* bl2 = (const float*)d_in[12];
    const float* Wr2 = (const float*)d_in[13];
    const float* Wl3 = (const float*)d_in[14];
    const float* bl3 = (const float*)d_in[15];
    const float* Wr3 = (const float*)d_in[16];
    const float* Wo  = (const float*)d_in[17];
    const float* bo  = (const float*)d_in[18];
    float* out = (float*)d_out;

    float *x0, *x1;
    __half *h0, *h1;
    cudaGetSymbolAddress((void**)&x0, g_x0);
    cudaGetSymbolAddress((void**)&x1, g_x1);
    cudaGetSymbolAddress((void**)&h0, g_h0);
    cudaGetSymbolAddress((void**)&h1, g_h1);

    const int TPB = 256;

    // graph prep (CSR rebuilt every replay: deterministic work)
    detect_kernel<<<1, 256>>>((const long long*)edge_idx);
    zero_cnt_kernel<<<(NN + TPB - 1) / TPB, TPB>>>();
    prep_edges_kernel<<<(NE + TPB - 1) / TPB, TPB>>>(edge_idx);
    scan1_kernel<<<NBLK, 1024>>>();
    scan2_kernel<<<1, 64>>>();
    scan3_kernel<<<NBLK, 1024>>>();
    csr_fill_kernel<<<(NE + TPB - 1) / TPB, TPB>>>();

    // input projection -> x0 / h0 [N,64]
    int projBlocks = (NN + 127) / 128;
    proj_kernel<768><<<projBlocks, TPB>>>(x_content, Wp, bp, x0, h0, 0);
    proj_kernel<128><<<projBlocks, TPB>>>(x_style, Ws, bs, x0, h0, 32);

    const int aggBlocks  = (NN * 32 + TPB - 1) / TPB;
    const int gemmBlocks = (NN + 63) / 64;

    // layer 1: (x0,h0) -> (x1,h1)
    aggregate_kernel<<<aggBlocks, TPB>>>(h0);
    layer_kernel<<<gemmBlocks, TPB>>>(x0, Wl1, bl1, Wr1, x1, h1);

    // layer 2: (x1,h1) -> (x0,h0)
    aggregate_kernel<<<aggBlocks, TPB>>>(h1);
    layer_kernel<<<gemmBlocks, TPB>>>(x1, Wl2, bl2, Wr2, x0, h0);

    // layer 3: (x0,h0) -> x1 (no fp16 needed)
    aggregate_kernel<<<aggBlocks, TPB>>>(h0);
    layer_kernel<<<gemmBlocks, TPB>>>(x0, Wl3, bl3, Wr3, x1, (\
__half*)nullptr);

    // head
    head_kernel<<<(NN * 32 + TPB - 1) / TPB, TPB>>>(x1, Wo, bo, out);
}

// round 5
// speedup vs baseline: 1.3762x; 1.0082x over previous
#include <cuda_runtime.h>
#include <cuda_fp16.h>
#include <stdint.h>

#define NN 50000
#define NE 1600000
#define D  64
#define NBLK 49   // ceil(NN/1024)

// ---------------- scratch (static device globals; no allocation) ----------------
__device__ __align__(16) float  g_x0[NN * D];
__device__ __align__(16) float  g_x1[NN * D];
__device__ __align__(16) __half g_h0[NN * D];   // fp16 shadow of x0
__device__ __align__(16) __half g_h1[NN * D];   // fp16 shadow of x1
__device__ __align__(16) float  g_acc[NN * D];
__device__ float g_invdeg[NN];
__device__ int   g_deg[NN];
__device__ int   g_fill[NN];
__device__ int   g_rowstart[NN + 1];
__device__ int   g_src[NE];
__device__ int   g_dst[NE];
__device__ int   g_csr[NE];
__device__ int   g_is64;
__device__ int   g_blocksum[NBLK];
__device__ int   g_blockbase[NBLK];

// ---------------- packed f32x2 helpers (sm_100+: FFMA2) ----------------
__device__ __forceinline__ unsigned long long dup2(float a) {
    unsigned long long r;
    asm("mov.b64 %0, {%1, %1};" : "=l"(r) : "f"(a));
    return r;
}
__device__ __forceinline__ void fma2(unsigned long long& d, unsigned long long a,
                                     unsigned long long b) {
    asm("fma.rn.f32x2 %0, %1, %2, %0;" : "+l"(d) : "l"(a), "l"(b));
}
__device__ __forceinline__ float2 ull2f2(unsigned long long v) {
    float2 f;
    asm("mov.b64 {%0, %1}, %2;" : "=f"(f.x), "=f"(f.y) : "l"(v));
    return f;
}

// ---------------- dtype probe: int64 vs int32 edge_index ----------------
__global__ void detect_kernel(const long long* __restrict__ p) {
    int t = threadIdx.x;              // 256 threads
    long long v = p[t];
    int ok = (v >= 0 && v < NN) ? 1 : 0;
    int all = __syncthreads_and(ok);
    if (t == 0) g_is64 = all;
}

// ---------------- zero counters ----------------
__global__ void zero_cnt_kernel() {
    int i = blockIdx.x * blockDim.x + threadIdx.x;
    if (i < NN) { g_deg[i] = 0; g_fill[i] = 0; }
}

// ---------------- edge prep: int64/int32 -> int32, degree count ----------------
__global__ void prep_edges_kernel(const void* __restrict__ ei) {
    int e = blockIdx.x * blockDim.x + threadIdx.x;
    if (e >= NE) return;
    int s, d;
    if (g_is64) {
        const long long* p = (const long long*)ei;
        s = (int)p[e];
        d = (int)p[NE + e];
    } else {
        const int* p = (const int*)ei;
        s = p[e];
        d = p[NE + e];
    }
    g_src[e] = s;
    g_dst[e] = d;
    atomicAdd(&g_deg[d], 1);
}

// ---------------- parallel exclusive scan over degrees (3 phases) ----------------
__global__ void scan1_kernel() {      // grid NBLK x 1024: block sums
    __shared__ int sh[1024];
    int t = threadIdx.x;
    int i = blockIdx.x * 1024 + t;
    int v = (i < NN) ? g_deg[i] : 0;
    sh[t] = v;
    __syncthreads();
#pragma unroll
    for (int off = 512; off > 0; off >>= 1) {
        if (t < off) sh[t] += sh[t + off];
        __syncthreads();
    }
    if (t == 0) g_blocksum[blockIdx.x] = sh[0];
}

__global__ void scan2_kernel() {      // 1 block x 64: scan of block sums
    __shared__ int sh[64];
    int t = threadIdx.x;
    int v = (t < NBLK) ? g_blocksum[t] : 0;
    sh[t] = v;
    __syncthreads();
#pragma unroll
    for (int off = 1; off < 64; off <<= 1) {
        int u = (t >= off) ? sh[t - off] : 0;
        __syncthreads();
        sh[t] += u;
        __syncthreads();
    }
    if (t < NBLK) g_blockbase[t] = sh[t] - v;   // exclusive base per block
    if (t == NBLK - 1) g_rowstart[NN] = sh[t];  // total = NE
}

__global__ void scan3_kernel() {      // grid NBLK x 1024: in-block scan + invdeg
    __shared__ int sh[1024];
    int t = threadIdx.x;
    int i = blockIdx.x * 1024 + t;
    int v = (i < NN) ? g_deg[i] : 0;
    sh[t] = v;
    __syncthreads();
#pragma unroll
    for (int off = 1; off < 1024; off <<= 1) {
        int u = (t >= off) ? sh[t - off] : 0;
        __syncthreads();
        sh[t] += u;
        __syncthreads();
    }
    if (i < NN) {
        g_rowstart[i] = g_blockbase[blockIdx.x] + sh[t] - v;
        g_invdeg[i] = 1.0f / fmaxf((float)v, 1.0f);
    }
}

// ---------------- CSR fill: csr[rowstart[dst] + k] = src ----------------
__global__ void csr_fill_kernel() {
    int e = blockIdx.x * blockDim.x + threadIdx.x;
    if (e >= NE) return;
    int d = g_dst[e];
    int slot = g_rowstart[d] + atomicAdd(&g_fill[d], 1);
    g_csr[slot] = g_src[e];
}

// ---------------- pack 4 floats into 4 halves (uint2) ----------------
__device__ __forceinline__ uint2 pack_half4(float a, float b, float c, float d) {
    __half2 lo = __floats2half2_rn(a, b);
    __half2 hi = __floats2half2_rn(c, d);
    uint2 r;
    r.x = *reinterpret_cast<uint32_t*>(&lo);
    r.y = *reinterpret_cast<uint32_t*>(&hi);
    return r;
}

// ---------------- input projection: out[:, colOff:colOff+32] = X @ W + b (+ fp16 shadow) ------
// BM=128 rows, BN=32 cols, BK=32. 256 threads; 4x4 micro-tile per thread; f32x2 FMA.
template <int DIN>
__global__ void proj_kernel(const float* __restrict__ X, const float* __restrict__ W,
                            const float* __restrict__ b, float* __restrict__ out,
                            __half* __restrict__ hout, int colOff) {
    __shared__ __align__(16) float sA[128][33];
    __shared__ __align__(16) float sW[32][32];
    const int t  = threadIdx.x;
    const int i0 = blockIdx.x * 128;
    const int tx = t & 7;    // col quad: cols tx*4 .. tx*4+3
    const int ty = t >> 3;   // 0..31: rows ty*4 .. ty*4+3

    unsigned long long racc2[4][2];
#pragma unroll
    for (int r = 0; r < 4; r++) { racc2[r][0] = 0ULL; racc2[r][1] = 0ULL; }

    const int c4 = t & 7;
    const int rl = t >> 3;

    for (int k0 = 0; k0 < DIN; k0 += 32) {
#pragma unroll
        for (int p = 0; p < 4; p++) {
            int row = rl + p * 32;
            int gi  = i0 + row;
            float4 v = make_float4(0.f, 0.f, 0.f, 0.f);
            if (gi < NN)
                v = *reinterpret_cast<const float4*>(&X[(size_t)gi * DIN + k0 + c4 * 4]);
            sA[row][c4 * 4 + 0] = v.x;
            sA[row][c4 * 4 + 1] = v.y;
            sA[row][c4 * 4 + 2] = v.z;
            sA[row][c4 * 4 + 3] = v.w;
        }
        {
            float4 w = *reinterpret_cast<const float4*>(&W[(size_t)(k0 + rl) * 32 + c4 * 4]);
            sW[rl][c4 * 4 + 0] = w.x;
            sW[rl][c4 * 4 + 1] = w.y;
            sW[rl][c4 * 4 + 2] = w.z;
            sW[rl][c4 * 4 + 3] = w.w;
        }
        __syncthreads();
#pragma unroll
        for (int kk = 0; kk < 32; kk++) {
            ulonglong2 wp = *reinterpret_cast<const ulonglong2*>(&sW[kk][tx * 4]);
            unsigned long long a0 = dup2(sA[ty * 4 + 0][kk]);
            unsigned long long a1 = dup2(sA[ty * 4 + 1][kk]);
            unsigned long long a2 = dup2(sA[ty * 4 + 2][kk]);
            unsigned long long a3 = dup2(sA[ty * 4 + 3][kk]);
            fma2(racc2[0][0], a0, wp.x); fma2(racc2[0][1], a0, wp.y);
            fma2(racc2[1][0], a1, wp.x); fma2(racc2[1][1], a1, wp.y);
            fma2(racc2[2][0], a2, wp.x); fma2(racc2[2][1], a2, wp.y);
            fma2(racc2[3][0], a3, wp.x); fma2(racc2[3][1], a3, wp.y);
        }
        __syncthreads();
    }

    float b0 = b[tx * 4 + 0], b1 = b[tx * 4 + 1], b2 = b[tx * 4 + 2], b3 = b[tx * 4 + 3];
#pragma unroll
    for (int r = 0; r < 4; r++) {
        int gi = i0 + ty * 4 + r;
        if (gi < NN) {
            float2 p0 = ull2f2(racc2[r][0]);
            float2 p1 = ull2f2(racc2[r][1]);
            float4 v;
            v.x = p0.x + b0;
            v.y = p0.y + b1;
            v.z = p1.x + b2;
            v.w = p1.y + b3;
            *reinterpret_cast<float4*>(&out[(size_t)gi * D + colOff + tx * 4]) = v;
            *reinterpret_cast<uint2*>(&hout[(size_t)gi * D + colOff + tx * 4]) =
                pack_half4(v.x, v.y, v.z, v.w);
        }
    }
}

// ---------------- gather aggregation (fp16 rows): acc[n] = invdeg[n]*sum xin_h[s] --------------
// warp per node; 4 neighbor streams x 8 lanes; lane loads uint4 = 8 halves (16B); row = 128B.
__global__ void aggregate_kernel(const __half* __restrict__ hin) {
    int warp = (blockIdx.x * blockDim.x + threadIdx.x) >> 5;
    int lane = threadIdx.x & 31;
    if (warp >= NN) return;
    const int q  = lane >> 3;   // stream 0..3
    const int l8 = lane & 7;    // 8-half chunk within row
    int beg = g_rowstart[warp];
    int end = g_rowstart[warp + 1];
    const uint4* h8 = reinterpret_cast<const uint4*>(hin);

    float acc[8];
#pragma unroll
    for (int k = 0; k < 8; k++) acc[k] = 0.f;

    int j = beg + q;
    for (; j + 4 < end; j += 8) {
        int s0 = g_csr[j];
        int s1 = g_csr[j + 4];
        uint4 a = __ldg(&h8[(size_t)s0 * 8 + l8]);
        uint4 b = __ldg(&h8[(size_t)s1 * 8 + l8]);
#pragma unroll
        for (int w = 0; w < 4; w++) {
            uint32_t ua = (&a.x)[w];
            uint32_t ub = (&b.x)[w];
            float2 fa = __half22float2(*reinterpret_cast<__half2*>(&ua));
            float2 fb = __half22float2(*reinterpret_cast<__half2*>(&ub));
            acc[w * 2 + 0] += fa.x + fb.x;
            acc[w * 2 + 1] += fa.y + fb.y;
        }
    }
    if (j < end) {
        int s0 = g_csr[j];
        uint4 a = __ldg(&h8[(size_t)s0 * 8 + l8]);
#pragma unroll
        for (int w = 0; w < 4; w++) {
            uint32_t ua = (&a.x)[w];
            float2 fa = __half22float2(*reinterpret_cast<__half2*>(&ua));
            acc[w * 2 + 0] += fa.x;
            acc[w * 2 + 1] += fa.y;
        }
    }
#pragma unroll
    for (int k = 0; k < 8; k++) {
        acc[k] += __shfl_xor_sync(0xFFFFFFFFu, acc[k], 8);
        acc[k] += __shfl_xor_sync(0xFFFFFFFFu, acc[k], 16);
    }
    if (q == 0) {
        float id = g_invdeg[warp];
        float4 v0 = make_float4(acc[0] * id, acc[1] * id, acc[2] * id, acc[3] * id);
        float4 v1 = make_float4(acc[4] * id, acc[5] * id, acc[6] * id, acc[7] * id);
        float4* dst = reinterpret_cast<float4*>(&g_acc[(size_t)warp * D + l8 * 8]);
        dst[0] = v0;
        dst[1] = v1;
    }
}

// ---------------- SAGE layer GEMM: xout = relu(acc @ Wl + xin @ Wr + bl) (+ fp16 shadow) ------
// f32x2 inner loop.
__global__ void layer_kernel(const float* __restrict__ xin, const float* __restrict__ Wl,
                             const float* __restrict__ bl, const float* __restrict__ Wr,
                             float* __restrict__ xout, __half* __restrict__ hout) {
    __shared__ __align__(16) float sA[64][65];
    __shared__ __align__(16) float sW[64][64];
    const int t  = threadIdx.x;
    const int i0 = blockIdx.x * 64;
    const int tx = t & 15;
    const int ty = t >> 4;

    unsigned long long racc2[4][2];
#pragma unroll
    for (int r = 0; r < 4; r++) { racc2[r][0] = 0ULL; racc2[r][1] = 0ULL; }

    const int c4 = t & 15;
    const int r0 = t >> 4;

    for (int half = 0; half < 2; half++) {
        const float* srcmat = (half == 0) ? g_acc : xin;
        const float* Wm     = (half == 0) ? Wl : Wr;
#pragma unroll
        for (int p = 0; p < 4; p++) {
            int row = r0 + p * 16;
            int gi  = i0 + row;
            float4 v = make_float4(0.f, 0.f, 0.f, 0.f);
            if (gi < NN)
                v = *reinterpret_cast<const float4*>(&srcmat[(size_t)gi * D + c4 * 4]);
            sA[row][c4 * 4 + 0] = v.x;
            sA[row][c4 * 4 + 1] = v.y;
            sA[row][c4 * 4 + 2] = v.z;
            sA[row][c4 * 4 + 3] = v.w;
        }
#pragma unroll
        for (int p = 0; p < 4; p++) {
            int row = r0 + p * 16;
            float4 w = *reinterpret_cast<const float4*>(&Wm[(size_t)row * 64 + c4 * 4]);
            sW[row][c4 * 4 + 0] = w.x;
            sW[row][c4 * 4 + 1] = w.y;
            sW[row][c4 * 4 + 2] = w.z;
            sW[row][c4 * 4 + 3] = w.w;
        }
        __syncthreads();
#pragma unroll
        for (int kk = 0; kk < 64; kk++) {
            ulonglong2 wp = *reinterpret_cast<const ulonglong2*>(&sW[kk][tx * 4]);
            unsigned long long a0 = dup2(sA[ty * 4 + 0][kk]);
            unsigned long long a1 = dup2(sA[ty * 4 + 1][kk]);
            unsigned long long a2 = dup2(sA[ty * 4 + 2][kk]);
            unsigned long long a3 = dup2(sA[ty * 4 + 3][kk]);
            fma2(racc2[0][0], a0, wp.x); fma2(racc2[0][1], a0, wp.y);
            fma2(racc2[1][0], a1, wp.x); fma2(racc2[1][1], a1, wp.y);
            fma2(racc2[2][0], a2, wp.x); fma2(racc2[2][1], a2, wp.y);
            fma2(racc2[3][0], a3, wp.x); fma2(racc2[3][1], a3, wp.y);
        }
        __syncthreads();
    }

    float b0 = bl[tx * 4 + 0], b1 = bl[tx * 4 + 1], b2 = bl[tx * 4 + 2], b3 = bl[tx * 4 + 3];
#pragma unroll
    for (int r = 0; r < 4; r++) {
        int gi = i0 + ty * 4 + r;
        if (gi < NN) {
            float2 p0 = ull2f2(racc2[r][0]);
            float2 p1 = ull2f2(racc2[r][1]);
            float4 v;
            v.x = fmaxf(p0.x + b0, 0.f);
            v.y = fmaxf(p0.y + b1, 0.f);
            v.z = fmaxf(p1.x + b2, 0.f);
            v.w = fmaxf(p1.y + b3, 0.f);
            *reinterpret_cast<float4*>(&xout[(size_t)gi * D + tx * 4]) = v;
            if (hout)
                *reinterpret_cast<uint2*>(&hout[(size_t)gi * D + tx * 4]) =
                    pack_half4(v.x, v.y, v.z, v.w);
        }
    }
}

// ---------------- output head: out = x @ Wo + bo   ([N,64]@[64,2]) ----------------
__global__ void head_kernel(const float* __restrict__ x, const float* __restrict__ Wo,
                            const float* __restrict__ bo, float* __restrict__ out) {
    int gw   = (blockIdx.x * blockDim.x + threadIdx.x) >> 5;
    int lane = threadIdx.x & 31;
    if (gw >= NN) return;
    float xa = x[(size_t)gw * D + lane];
    float xb = x[(size_t)gw * D + 32 + lane];
    float p0 = xa * Wo[lane * 2 + 0] + xb * Wo[(lane + 32) * 2 + 0];
    float p1 = xa * Wo[lane * 2 + 1] + xb * Wo[(lane + 32) * 2 + 1];
#pragma unroll
    for (int o = 16; o > 0; o >>= 1) {
        p0 += __shfl_xor_sync(0xFFFFFFFFu, p0, o);
        p1 += __shfl_xor_sync(0xFFFFFFFFu, p1, o);
    }
    if (lane == 0) {
        out[gw * 2 + 0] = p0 + bo[0];
        out[gw * 2 + 1] = p1 + bo[1];
    }
}

// ---------------- launch ----------------
extern "C" void kernel_launch(void* const* d_in, const int* in_sizes, int n_in,
                              void* d_out, int out_size) {
    const float* x_content = (const float*)d_in[0];
    const float* x_style   = (const float*)d_in[1];
    const void*  edge_idx  = d_in[2];
    // d_in[3] = edge_type (unused by the model)
    const float* Wp  = (const float*)d_in[4];
    const float* bp  = (const float*)d_in[5];
    const float* Ws  = (const float*)d_in[6];
    const float* bs  = (const float*)d_in[7];
    const float* Wl1 = (const float*)d_in[8];
    const float* bl1 = (const float*)d_in[9];
    const float* Wr1 = (const float*)d_in[10];
    const float* Wl2 = (const float*)d_in[11];
    const float* bl2 = (const float*)d_in[12];
    const float* Wr2 = (const float*)d_in[13];
    const float* Wl3 = (const float*)d_in[14];
    const float* bl3 = (const float*)d_in[15];
    const float* Wr3 = (const float*)d_in[16];
    const float* Wo  = (const float*)d_in[17];
    const float* bo  = (const float*)d_in[18];
    float* out = (float*)d_out;

    float *x0, *x1;
    __half *h0, *h1;
    cudaGetSymbolAddress((void**)&x0, g_x0);
    cudaGetSymbolAddress((void**)&x1, g_x1);
    cudaGetSymbolAddress((void**)&h0, g_h0);
    cudaGetSymbolAddress((void**)&h1, g_h1);

    const int TPB = 256;

    // graph prep (CSR rebuilt every replay: deterministic work)
    detect_kernel<<<1, 256>>>((const long long*)edge_idx);
    zero_cnt_kernel<<<(NN + TPB - 1) / TPB, TPB>>>();
    prep_edges_kernel<<<(NE + TPB - 1) / TPB, TPB>>>(edge_idx);
    scan1_kernel<<<NBLK, 1024>>>();
    scan2_kernel<<<1, 64>>>();
    scan3_kernel<<<NBLK, 1024>>>();
    csr_fill_kernel<<<(NE + TPB - 1) / TPB, TPB>>>();

    // input projection -> x0 / h0 [N,64]
    int projBlocks = (NN + 127) / 128;
    proj_kernel<768><<<projBlocks, TPB>>>(x_content, Wp, bp, x0, h0, 0);
    proj_kernel<128><<<projBlocks, TPB>>>(x_style, Ws, bs, x0, h0, 32);

    const int aggBlocks  = (NN * 32 + TPB - 1) / TPB;
    const int gemmBlocks = (NN + 63) / 64;

    // layer 1: (x0,h0) -> (x1,h1)
    aggregate_kernel<<<aggBlocks, TPB>>>(h0);
    layer_kernel<<<gemmBlocks, TPB>>>(x0, Wl1, bl1, Wr1, x1, h1);

    // layer 2: (x1,h1) -> (x0,h0)
    aggregate_kernel<<<aggBlocks, TPB>>>(h1);
    layer_kernel<<<gemmBlocks, TPB>>>(x1, Wl2, bl2, Wr2, x0, h0);

    // layer 3: (x0,h0) -> x1 (no fp16 needed)
    aggregate_kernel<<<aggBlocks, TPB>>>(h0);
    layer_kernel<<<gemmBlocks, TPB>>>(x0, Wl3, bl3, Wr3, x1, (__half*)nullptr);

    // head
    head_kernel<<<(NN * 32 + TPB - 1) / TPB, TPB>>>(x1, Wo, bo, out);
}